// round 14
// baseline (speedup 1.0000x reference)
#include <cuda_runtime.h>
#include <cuda_fp16.h>
#include <cstdint>

#define NN 50000
#define NE 800000
#define INC 165
#define HID 256
#define KP1 192              // K=165 padded to multiple of 64

// ---------------- scratch (no runtime allocation allowed) ----------------
__device__ int   g_cnt[NN];
__device__ int   g_ptr[NN + 1];
__device__ int   g_cursor[NN];
__device__ int   g_csr[NE];
__device__ __half g_x [(size_t)NN * KP1];
__device__ __half g_h1[(size_t)NN * HID];
__device__ __half g_h [(size_t)NN * HID];
__device__ __half g_w1a[HID * KP1];
__device__ __half g_w1b[HID * HID];
__device__ __half g_w2a[HID * HID];

// ---------------- PTX helpers ----------------
__device__ __forceinline__ uint32_t smem_u32(const void* p) {
    uint32_t a;
    asm("{ .reg .u64 t; cvta.to.shared.u64 t, %1; cvt.u32.u64 %0, t; }" : "=r"(a) : "l"(p));
    return a;
}
__device__ __forceinline__ void ldm_x4(uint32_t* r, uint32_t addr) {
    asm volatile("ldmatrix.sync.aligned.m8n8.x4.shared.b16 {%0,%1,%2,%3}, [%4];"
        : "=r"(r[0]), "=r"(r[1]), "=r"(r[2]), "=r"(r[3]) : "r"(addr));
}
__device__ __forceinline__ void ldm_x2(uint32_t* r, uint32_t addr) {
    asm volatile("ldmatrix.sync.aligned.m8n8.x2.shared.b16 {%0,%1}, [%2];"
        : "=r"(r[0]), "=r"(r[1]) : "r"(addr));
}
__device__ __forceinline__ void mma_f16(float* c, const uint32_t* a, const uint32_t* b) {
    asm volatile("mma.sync.aligned.m16n8k16.row.col.f32.f16.f16.f32 "
        "{%0,%1,%2,%3}, {%4,%5,%6,%7}, {%8,%9}, {%0,%1,%2,%3};"
        : "+f"(c[0]), "+f"(c[1]), "+f"(c[2]), "+f"(c[3])
        : "r"(a[0]), "r"(a[1]), "r"(a[2]), "r"(a[3]), "r"(b[0]), "r"(b[1]));
}
__device__ __forceinline__ void cp16(uint32_t dst, const void* src) {
    asm volatile("cp.async.ca.shared.global [%0], [%1], 16;" :: "r"(dst), "l"(src));
}
__device__ __forceinline__ uint32_t pack2h(float v0, float v1) {
    __half2 h = __floats2half2_rn(v0, v1);
    return *(uint32_t*)&h;
}
__device__ __forceinline__ void acc8(float* a, uint4 h) {
    const uint32_t hu[4] = {h.x, h.y, h.z, h.w};
#pragma unroll
    for (int q = 0; q < 4; q++) {
        float2 fh = __half22float2(*(const __half2*)&hu[q]);
        a[2 * q]     += fh.x;
        a[2 * q + 1] += fh.y;
    }
}

// ---------------------------------------------------------------------------
// CSR build (1 edge per thread — R12 showed ILP-4 regresses here)
// ---------------------------------------------------------------------------
__global__ void hist_kernel(const int* __restrict__ dst, int* __restrict__ cnt) {
    int e = blockIdx.x * blockDim.x + threadIdx.x;
    if (e < NE) atomicAdd(&cnt[__ldg(dst + e)], 1);
}

__global__ void scan_kernel(const int* __restrict__ cnt,
                            int* __restrict__ ptr, int* __restrict__ cursor) {
    __shared__ int wsum[32];
    __shared__ int running;
    const int t = threadIdx.x;
    if (t == 0) running = 0;
    __syncthreads();
    for (int base = 0; base < NN; base += 1024) {
        int v = (base + t < NN) ? cnt[base + t] : 0;
        int x = v;
#pragma unroll
        for (int o = 1; o < 32; o <<= 1) {
            int y = __shfl_up_sync(0xffffffffu, x, o);
            if ((t & 31) >= o) x += y;
        }
        if ((t & 31) == 31) wsum[t >> 5] = x;
        __syncthreads();
        if (t < 32) {
            int w = wsum[t];
#pragma unroll
            for (int o = 1; o < 32; o <<= 1) {
                int y = __shfl_up_sync(0xffffffffu, w, o);
                if (t >= o) w += y;
            }
            wsum[t] = w;
        }
        __syncthreads();
        int excl = x - v + ((t >= 32) ? wsum[(t >> 5) - 1] : 0) + running;
        if (base + t < NN) { ptr[base + t] = excl; cursor[base + t] = excl; }
        __syncthreads();
        if (t == 0) running += wsum[31];
        __syncthreads();
    }
    if (t == 0) ptr[NN] = running;
}

__global__ void fill_kernel(const int* __restrict__ src, const int* __restrict__ dst,
                            int* __restrict__ cursor, int* __restrict__ csr) {
    int e = blockIdx.x * blockDim.x + threadIdx.x;
    if (e < NE) {
        int p = atomicAdd(&cursor[__ldg(dst + e)], 1);
        csr[p] = __ldg(src + e);
    }
}

// x [NN][165] fp32 -> fp16 [NN][192], zero-padded
__global__ void pad_kernel(const float* __restrict__ x, __half* __restrict__ xo) {
    int i = blockIdx.x * blockDim.x + threadIdx.x;
    if (i >= NN * (KP1 / 4)) return;
    int n = i / (KP1 / 4), c = (i % (KP1 / 4)) * 4;
    float v[4];
#pragma unroll
    for (int q = 0; q < 4; q++) {
        int cc = c + q;
        v[q] = (cc < INC) ? __ldg(&x[(size_t)n * INC + cc]) : 0.f;
    }
    *(uint32_t*)(xo + (size_t)n * KP1 + c)     = pack2h(v[0], v[1]);
    *(uint32_t*)(xo + (size_t)n * KP1 + c + 2) = pack2h(v[2], v[3]);
}

// ---------------------------------------------------------------------------
// All-in-one prep: 3 weight transposes/casts + out bias init (segmented).
// ---------------------------------------------------------------------------
#define PW1 (HID * KP1)        // 49152
#define PW2 (HID * HID)        // 65536
#define PTOT (PW1 + 2 * PW2 + NN * 2)

__global__ void prep_all_kernel(const float* __restrict__ W1a,
                                const float* __restrict__ W1b,
                                const float* __restrict__ W2a,
                                const float* __restrict__ b2b,
                                __half* __restrict__ w1a,
                                __half* __restrict__ w1b,
                                __half* __restrict__ w2a,
                                float* __restrict__ out) {
    int i = blockIdx.x * blockDim.x + threadIdx.x;
    if (i < PW1) {
        int n = i / KP1, k = i % KP1;
        float w = (k < INC) ? __ldg(&W1a[(size_t)k * HID + n]) : 0.f;
        w1a[i] = __float2half_rn(w);
        return;
    }
    i -= PW1;
    if (i < PW2) {
        int n = i / HID, k = i % HID;
        w1b[i] = __float2half_rn(__ldg(&W1b[(size_t)k * HID + n]));
        return;
    }
    i -= PW2;
    if (i < PW2) {
        int n = i / HID, k = i % HID;
        w2a[i] = __float2half_rn(__ldg(&W2a[(size_t)k * HID + n]));
        return;
    }
    i -= PW2;
    if (i < NN * 2) out[i] = __ldg(b2b + (i & 1));
}

// ---------------------------------------------------------------------------
// Fused gather + GEMM: CTA owns 128 nodes; gathers z = f[n] + sum_nbr f[nbr]
// into an fp16 smem A-tile, then computes relu(z @ W + bias) for all N=256.
// 512 threads = 16 warps (4M x 4N), warp tile 32x64. B double-buffered via
// cp.async (first two chunks prefetched BEFORE the gather phase).
// Non-OUTP: store fp16 C. OUTP: project on w2[256][2], atomicAdd into Cout.
// ---------------------------------------------------------------------------
#define SROW 72
#define BSTG (256 * SROW * 2)      // 36864 B per B stage

template<int KP, bool OUTP>
__global__ __launch_bounds__(512, 1)
void fused_gather_gemm(const uint4* __restrict__ F,      // [NN][KP/8] fp16 rows
                       const int* __restrict__ ptr, const int* __restrict__ csr,
                       const __half* __restrict__ B,     // W^T [256][KP]
                       const float* __restrict__ bias,
                       __half* __restrict__ C,
                       float* __restrict__ Cout, int M,
                       const float* __restrict__ w2) {
    constexpr int AROW = KP + 8;           // smem A row stride (halves)
    constexpr int RU4 = KP / 8;            // uint4s per feature row
    constexpr int NCH = KP / 64;           // B chunks
    extern __shared__ __align__(16) char smem[];
    const uint32_t sbA = smem_u32(smem);
    const uint32_t sbB = sbA + (uint32_t)(128 * AROW * 2);

    const int tid = threadIdx.x, wid = tid >> 5, lane = tid & 31;
    const int bm0 = blockIdx.x * 128;

    // ---- B prefetch mapping (512 threads: row=tid>>1, 32 halves each) ----
    const int brow = tid >> 1;
    const int bcol0 = (tid & 1) * 32;
    const __half* pB = B + (size_t)brow * KP + bcol0;
    const uint32_t sdstB = sbB + (uint32_t)(brow * SROW + bcol0) * 2;

#define PREFETCH_B(CH)  do { \
        const int _k0 = (CH) << 6; \
        const uint32_t _d = sdstB + ((CH) & 1) * BSTG; \
        _Pragma("unroll") \
        for (int q = 0; q < 4; q++) cp16(_d + q * 16, pB + _k0 + q * 8); \
    } while (0)

    PREFETCH_B(0);
    asm volatile("cp.async.commit_group;" ::: "memory");
    PREFETCH_B(1);
    asm volatile("cp.async.commit_group;" ::: "memory");

    // ---- gather phase: 16 warps x 8 nodes -> fp16 A-tile in smem ----
    for (int i = 0; i < 8; i++) {
        const int row = wid * 8 + i;           // 0..127
        const int n = bm0 + row;
        if (lane < RU4) {
            float a[8] = {0, 0, 0, 0, 0, 0, 0, 0};
            if (n < M) {
                acc8(a, __ldg(F + (size_t)n * RU4 + lane));
                const int e0 = __ldg(ptr + n), e1 = __ldg(ptr + n + 1);
                int j = e0;
                for (; j + 3 < e1; j += 4) {
                    const size_t b0 = (size_t)__ldg(csr + j)     * RU4;
                    const size_t b1 = (size_t)__ldg(csr + j + 1) * RU4;
                    const size_t b2 = (size_t)__ldg(csr + j + 2) * RU4;
                    const size_t b3 = (size_t)__ldg(csr + j + 3) * RU4;
                    uint4 v0 = __ldg(F + b0 + lane), v1 = __ldg(F + b1 + lane);
                    uint4 v2 = __ldg(F + b2 + lane), v3 = __ldg(F + b3 + lane);
                    acc8(a, v0); acc8(a, v1); acc8(a, v2); acc8(a, v3);
                }
                for (; j < e1; j++)
                    acc8(a, __ldg(F + (size_t)__ldg(csr + j) * RU4 + lane));
            }
            uint4 o;
            o.x = pack2h(a[0], a[1]);
            o.y = pack2h(a[2], a[3]);
            o.z = pack2h(a[4], a[5]);
            o.w = pack2h(a[6], a[7]);
            *(uint4*)(smem + (uint32_t)row * (AROW * 2) + lane * 16) = o;
        }
    }
    __syncthreads();

    // ---- GEMM phase ----
    const int mw = (wid >> 2) * 32;
    const int nw = (wid & 3) * 64;

    float acc[2][8][4];
#pragma unroll
    for (int ms = 0; ms < 2; ms++)
#pragma unroll
        for (int ns = 0; ns < 8; ns++)
#pragma unroll
            for (int q = 0; q < 4; q++) acc[ms][ns][q] = 0.f;

    const int l7 = lane & 7;
    const int aRowAdd = ((lane >> 3) & 1) * 8;
    const int aKAdd = (lane >> 4) * 8;
    const int bl = lane & 15;
    const int bRow = bl & 7;
    const int bKAdd = ((bl >> 3) & 1) * 8;

    for (int ch = 0; ch < NCH; ch++) {
        asm volatile("cp.async.wait_group 1;" ::: "memory");
        __syncthreads();
        const uint32_t stB = sbB + (ch & 1) * BSTG;
        const int kg0 = ch << 6;
#pragma unroll
        for (int kk = 0; kk < 64; kk += 16) {
            uint32_t av[2][4], bv[8][2];
#pragma unroll
            for (int ms = 0; ms < 2; ms++) {
                uint32_t ra = sbA +
                    (uint32_t)((mw + ms * 16 + l7 + aRowAdd) * AROW + kg0 + kk + aKAdd) * 2;
                ldm_x4(av[ms], ra);
            }
#pragma unroll
            for (int ns = 0; ns < 8; ns++) {
                uint32_t rb = stB + (uint32_t)((nw + ns * 8 + bRow) * SROW + kk + bKAdd) * 2;
                ldm_x2(bv[ns], rb);
            }
#pragma unroll
            for (int ms = 0; ms < 2; ms++)
#pragma unroll
                for (int ns = 0; ns < 8; ns++)
                    mma_f16(acc[ms][ns], av[ms], bv[ns]);
        }
        __syncthreads();
        if (ch + 2 < NCH) PREFETCH_B(ch + 2);
        asm volatile("cp.async.commit_group;" ::: "memory");
    }
#undef PREFETCH_B

    const int r = lane >> 2;
    const int cp = (lane & 3) * 2;

    if (OUTP) {
        float s[2][2][2];
#pragma unroll
        for (int ms = 0; ms < 2; ms++)
#pragma unroll
            for (int rh = 0; rh < 2; rh++) { s[ms][rh][0] = 0.f; s[ms][rh][1] = 0.f; }
#pragma unroll
        for (int ms = 0; ms < 2; ms++)
#pragma unroll
            for (int ns = 0; ns < 8; ns++) {
                const int col = nw + ns * 8 + cp;
                const float2 bb = *(const float2*)(bias + col);
                const float2 w0 = *(const float2*)(w2 + col * 2);
                const float2 w1 = *(const float2*)(w2 + (col + 1) * 2);
                float v0 = fmaxf(acc[ms][ns][0] + bb.x, 0.f);
                float v1 = fmaxf(acc[ms][ns][1] + bb.y, 0.f);
                float v2 = fmaxf(acc[ms][ns][2] + bb.x, 0.f);
                float v3 = fmaxf(acc[ms][ns][3] + bb.y, 0.f);
                s[ms][0][0] += v0 * w0.x + v1 * w1.x;
                s[ms][0][1] += v0 * w0.y + v1 * w1.y;
                s[ms][1][0] += v2 * w0.x + v3 * w1.x;
                s[ms][1][1] += v2 * w0.y + v3 * w1.y;
            }
#pragma unroll
        for (int ms = 0; ms < 2; ms++)
#pragma unroll
            for (int rh = 0; rh < 2; rh++)
#pragma unroll
                for (int oc = 0; oc < 2; oc++) {
                    float v = s[ms][rh][oc];
                    v += __shfl_xor_sync(0xffffffffu, v, 1);
                    v += __shfl_xor_sync(0xffffffffu, v, 2);
                    s[ms][rh][oc] = v;
                }
        if ((lane & 3) == 0) {
#pragma unroll
            for (int ms = 0; ms < 2; ms++)
#pragma unroll
                for (int rh = 0; rh < 2; rh++) {
                    const int row = bm0 + mw + ms * 16 + r + rh * 8;
                    if (row < M) {
                        atomicAdd(Cout + (size_t)row * 2 + 0, s[ms][rh][0]);
                        atomicAdd(Cout + (size_t)row * 2 + 1, s[ms][rh][1]);
                    }
                }
        }
    } else {
#pragma unroll
        for (int ms = 0; ms < 2; ms++)
#pragma unroll
            for (int ns = 0; ns < 8; ns++) {
                const int col = nw + ns * 8 + cp;
                const float2 bb = *(const float2*)(bias + col);
                const int row0 = bm0 + mw + ms * 16 + r;
                float v0 = fmaxf(acc[ms][ns][0] + bb.x, 0.f);
                float v1 = fmaxf(acc[ms][ns][1] + bb.y, 0.f);
                float v2 = fmaxf(acc[ms][ns][2] + bb.x, 0.f);
                float v3 = fmaxf(acc[ms][ns][3] + bb.y, 0.f);
#pragma unroll
                for (int rh = 0; rh < 2; rh++) {
                    const int row = row0 + rh * 8;
                    if (row >= M) continue;
                    *(uint32_t*)(C + (size_t)row * HID + col) =
                        pack2h(rh ? v2 : v0, rh ? v3 : v1);
                }
            }
    }
}

// ---------------------------------------------------------------------------
// Plain 2-stage pipelined GEMM for layer-1 second linear (h1 -> h).
// ---------------------------------------------------------------------------
#define SMAT (128 * SROW * 2)
#define OFF_A 0
#define OFF_B (SMAT)
#define STG (2 * SMAT)
#define SMTOT2 (2 * STG)           // 73728 B

__global__ __launch_bounds__(256, 2)
void mma_gemm_kernel(const __half* __restrict__ A, int lda,
                     const __half* __restrict__ B, int Kp,
                     const float* __restrict__ bias,
                     __half* __restrict__ C, int M) {
    extern __shared__ __align__(16) char smem[];
    const uint32_t sb = smem_u32(smem);
    const int tid = threadIdx.x, wid = tid >> 5, lane = tid & 31;

    const int bm0 = blockIdx.y * 128;
    const int n0 = blockIdx.x * 128;

    const int arow = tid >> 1;
    const int acol0 = (tid & 1) * 32;
    const int mw = (wid >> 1) * 32;
    const int nw = (wid & 1) * 64;

    const int gRow = bm0 + arow;
    const __half* pA = A + (size_t)(gRow < M ? gRow : 0) * lda + acol0;
    const __half* pB = B + (size_t)(n0 + arow) * Kp + acol0;
    const uint32_t sdst = sb + (uint32_t)(arow * SROW + acol0) * 2;

    const int nchunks = Kp >> 6;

#define PREFETCH(CH)  do { \
        const int _k0 = (CH) << 6; \
        const uint32_t _d = sdst + ((CH) & 1) * STG; \
        _Pragma("unroll") \
        for (int q = 0; q < 4; q++) { \
            cp16(_d + OFF_A + q * 16, pA + _k0 + q * 8); \
            cp16(_d + OFF_B + q * 16, pB + _k0 + q * 8); \
        } \
    } while (0)

    PREFETCH(0);
    asm volatile("cp.async.commit_group;" ::: "memory");
    PREFETCH(1);
    asm volatile("cp.async.commit_group;" ::: "memory");

    float acc[2][8][4];
#pragma unroll
    for (int ms = 0; ms < 2; ms++)
#pragma unroll
        for (int ns = 0; ns < 8; ns++)
#pragma unroll
            for (int q = 0; q < 4; q++) acc[ms][ns][q] = 0.f;

    const int l7 = lane & 7;
    const int aRowAdd = ((lane >> 3) & 1) * 8;
    const int aKAdd = (lane >> 4) * 8;
    const int bl = lane & 15;
    const int bRow = bl & 7;
    const int bKAdd = ((bl >> 3) & 1) * 8;

    for (int ch = 0; ch < nchunks; ch++) {
        asm volatile("cp.async.wait_group 1;" ::: "memory");
        __syncthreads();

        const uint32_t st = sb + (ch & 1) * STG;
#pragma unroll
        for (int kk = 0; kk < 64; kk += 16) {
            uint32_t av[2][4], bv[8][2];
#pragma unroll
            for (int ms = 0; ms < 2; ms++) {
                uint32_t ra = st + (uint32_t)((mw + ms * 16 + l7 + aRowAdd) * SROW + kk + aKAdd) * 2;
                ldm_x4(av[ms], ra + OFF_A);
            }
#pragma unroll
            for (int ns = 0; ns < 8; ns++) {
                uint32_t rb = st + (uint32_t)((nw + ns * 8 + bRow) * SROW + kk + bKAdd) * 2;
                ldm_x2(bv[ns], rb + OFF_B);
            }
#pragma unroll
            for (int ms = 0; ms < 2; ms++)
#pragma unroll
                for (int ns = 0; ns < 8; ns++)
                    mma_f16(acc[ms][ns], av[ms], bv[ns]);
        }
        __syncthreads();
        if (ch + 2 < nchunks) PREFETCH(ch + 2);
        asm volatile("cp.async.commit_group;" ::: "memory");
    }
#undef PREFETCH

    const int r = lane >> 2;
    const int cp = (lane & 3) * 2;
#pragma unroll
    for (int ms = 0; ms < 2; ms++)
#pragma unroll
        for (int ns = 0; ns < 8; ns++) {
            const int col = n0 + nw + ns * 8 + cp;
            const float2 bb = *(const float2*)(bias + col);
            const int row0 = bm0 + mw + ms * 16 + r;
            float v0 = fmaxf(acc[ms][ns][0] + bb.x, 0.f);
            float v1 = fmaxf(acc[ms][ns][1] + bb.y, 0.f);
            float v2 = fmaxf(acc[ms][ns][2] + bb.x, 0.f);
            float v3 = fmaxf(acc[ms][ns][3] + bb.y, 0.f);
#pragma unroll
            for (int rh = 0; rh < 2; rh++) {
                const int row = row0 + rh * 8;
                if (row >= M) continue;
                *(uint32_t*)(C + (size_t)row * HID + col) =
                    pack2h(rh ? v2 : v0, rh ? v3 : v1);
            }
        }
}

// ---------------------------------------------------------------------------
extern "C" void kernel_launch(void* const* d_in, const int* in_sizes, int n_in,
                              void* d_out, int out_size) {
    const float* x   = (const float*)d_in[0];
    const int*   ei  = (const int*)d_in[1];
    const float* W1a = (const float*)d_in[2];
    const float* b1a = (const float*)d_in[3];
    const float* W1b = (const float*)d_in[4];
    const float* b1b = (const float*)d_in[5];
    const float* W2a = (const float*)d_in[6];
    const float* b2a = (const float*)d_in[7];
    const float* W2b = (const float*)d_in[8];
    const float* b2b = (const float*)d_in[9];
    float* out = (float*)d_out;

    const int* src = ei;
    const int* dst = ei + NE;

    int *cnt, *ptr, *cursor, *csr;
    __half *xp, *h1, *h, *w1a, *w1b, *w2a;
    cudaGetSymbolAddress((void**)&cnt,    g_cnt);
    cudaGetSymbolAddress((void**)&ptr,    g_ptr);
    cudaGetSymbolAddress((void**)&cursor, g_cursor);
    cudaGetSymbolAddress((void**)&csr,    g_csr);
    cudaGetSymbolAddress((void**)&xp,     g_x);
    cudaGetSymbolAddress((void**)&h1,     g_h1);
    cudaGetSymbolAddress((void**)&h,      g_h);
    cudaGetSymbolAddress((void**)&w1a,    g_w1a);
    cudaGetSymbolAddress((void**)&w1b,    g_w1b);
    cudaGetSymbolAddress((void**)&w2a,    g_w2a);

    // smem sizes: fused1 = 128*200*2 + 2*36864 = 124928; fused3 = 128*264*2 + 2*36864 = 141312
    const int SM_F1 = 128 * (KP1 + 8) * 2 + 2 * BSTG;
    const int SM_F3 = 128 * (HID + 8) * 2 + 2 * BSTG;
    cudaFuncSetAttribute(fused_gather_gemm<KP1, false>,
                         cudaFuncAttributeMaxDynamicSharedMemorySize, SM_F1);
    cudaFuncSetAttribute(fused_gather_gemm<HID, true>,
                         cudaFuncAttributeMaxDynamicSharedMemorySize, SM_F3);
    cudaFuncSetAttribute(mma_gemm_kernel,
                         cudaFuncAttributeMaxDynamicSharedMemorySize, SMTOT2);

    const int fusedGrid = (NN + 127) / 128;     // 391
    const dim3 gemm2Grid(2, (NN + 127) / 128);
    const int edgeGrid = (NE + 255) / 256;

    // ---- CSR build + pad x + all prep ----
    cudaMemsetAsync(cnt, 0, sizeof(int) * NN);
    hist_kernel<<<edgeGrid, 256>>>(dst, cnt);
    pad_kernel<<<(NN * (KP1 / 4) + 255) / 256, 256>>>(x, xp);
    scan_kernel<<<1, 1024>>>(cnt, ptr, cursor);
    fill_kernel<<<edgeGrid, 256>>>(src, dst, cursor, csr);
    prep_all_kernel<<<(PTOT + 255) / 256, 256>>>(W1a, W1b, W2a, b2b, w1a, w1b, w2a, out);

    // ---- layer 1: fused gather+GEMM, then plain GEMM ----
    fused_gather_gemm<KP1, false><<<fusedGrid, 512, SM_F1>>>(
        (const uint4*)xp, ptr, csr, w1a, b1a, h1, nullptr, NN, nullptr);
    mma_gemm_kernel<<<gemm2Grid, 256, SMTOT2>>>(h1, HID, w1b, HID, b1b, h, NN);

    // ---- layer 2: fused gather+GEMM with output projection ----
    fused_gather_gemm<HID, true><<<fusedGrid, 512, SM_F3>>>(
        (const uint4*)h, ptr, csr, w2a, b2a, nullptr, out, NN, W2b);
}

// round 15
// speedup vs baseline: 1.1763x; 1.1763x over previous
#include <cuda_runtime.h>
#include <cuda_fp16.h>
#include <cstdint>

#define NN 50000
#define NE 800000
#define INC 165
#define HID 256
#define KP1 192              // K=165 padded to multiple of 64

// ---------------- scratch (no runtime allocation allowed) ----------------
__device__ int   g_cnt[NN];
__device__ int   g_ptr[NN + 1];
__device__ int   g_cursor[NN];
__device__ int   g_csr[NE];
__device__ __half g_x [(size_t)NN * KP1];
__device__ __half g_z1[(size_t)NN * KP1];
__device__ __half g_h1[(size_t)NN * HID];
__device__ __half g_h [(size_t)NN * HID];
__device__ __half g_z2[(size_t)NN * HID];
__device__ __half g_w1a[HID * KP1];
__device__ __half g_w1b[HID * HID];
__device__ __half g_w2a[HID * HID];

// ---------------- PTX helpers ----------------
__device__ __forceinline__ uint32_t smem_u32(const void* p) {
    uint32_t a;
    asm("{ .reg .u64 t; cvta.to.shared.u64 t, %1; cvt.u32.u64 %0, t; }" : "=r"(a) : "l"(p));
    return a;
}
__device__ __forceinline__ void ldm_x4(uint32_t* r, uint32_t addr) {
    asm volatile("ldmatrix.sync.aligned.m8n8.x4.shared.b16 {%0,%1,%2,%3}, [%4];"
        : "=r"(r[0]), "=r"(r[1]), "=r"(r[2]), "=r"(r[3]) : "r"(addr));
}
__device__ __forceinline__ void ldm_x2(uint32_t* r, uint32_t addr) {
    asm volatile("ldmatrix.sync.aligned.m8n8.x2.shared.b16 {%0,%1}, [%2];"
        : "=r"(r[0]), "=r"(r[1]) : "r"(addr));
}
__device__ __forceinline__ void mma_f16(float* c, const uint32_t* a, const uint32_t* b) {
    asm volatile("mma.sync.aligned.m16n8k16.row.col.f32.f16.f16.f32 "
        "{%0,%1,%2,%3}, {%4,%5,%6,%7}, {%8,%9}, {%0,%1,%2,%3};"
        : "+f"(c[0]), "+f"(c[1]), "+f"(c[2]), "+f"(c[3])
        : "r"(a[0]), "r"(a[1]), "r"(a[2]), "r"(a[3]), "r"(b[0]), "r"(b[1]));
}
__device__ __forceinline__ void cp16(uint32_t dst, const void* src) {
    asm volatile("cp.async.ca.shared.global [%0], [%1], 16;" :: "r"(dst), "l"(src));
}
__device__ __forceinline__ uint32_t pack2h(float v0, float v1) {
    __half2 h = __floats2half2_rn(v0, v1);
    return *(uint32_t*)&h;
}
__device__ __forceinline__ void acc8(float* a, uint4 h) {
    const uint32_t hu[4] = {h.x, h.y, h.z, h.w};
#pragma unroll
    for (int q = 0; q < 4; q++) {
        float2 fh = __half22float2(*(const __half2*)&hu[q]);
        a[2 * q]     += fh.x;
        a[2 * q + 1] += fh.y;
    }
}

// ---------------------------------------------------------------------------
// Stage A (merged): hist over edges + pad/convert x. Disjoint thread ranges.
// ---------------------------------------------------------------------------
#define PADN (NN * (KP1 / 4))          // 2,400,000 pad work-items (4 cols each)
#define STAGEA_TOT (NE + PADN)

__global__ void hist_pad_kernel(const int* __restrict__ dst,
                                const float* __restrict__ x,
                                int* __restrict__ cnt,
                                __half* __restrict__ xo) {
    int i = blockIdx.x * blockDim.x + threadIdx.x;
    if (i < NE) {
        atomicAdd(&cnt[__ldg(dst + i)], 1);
        return;
    }
    i -= NE;
    if (i >= PADN) return;
    int n = i / (KP1 / 4), c = (i % (KP1 / 4)) * 4;
    float v[4];
#pragma unroll
    for (int q = 0; q < 4; q++) {
        int cc = c + q;
        v[q] = (cc < INC) ? __ldg(&x[(size_t)n * INC + cc]) : 0.f;
    }
    *(uint32_t*)(xo + (size_t)n * KP1 + c)     = pack2h(v[0], v[1]);
    *(uint32_t*)(xo + (size_t)n * KP1 + c + 2) = pack2h(v[2], v[3]);
}

// ---------------------------------------------------------------------------
// Scan: single block, 4 elements/thread per iteration (13 iterations).
// ---------------------------------------------------------------------------
__global__ void scan_kernel(const int* __restrict__ cnt,
                            int* __restrict__ ptr, int* __restrict__ cursor) {
    __shared__ int wsum[32];
    __shared__ int running;
    const int t = threadIdx.x;
    if (t == 0) running = 0;
    __syncthreads();
    for (int base = 0; base < NN; base += 4096) {
        const int idx = base + t * 4;
        int v[4];
#pragma unroll
        for (int q = 0; q < 4; q++)
            v[q] = (idx + q < NN) ? cnt[idx + q] : 0;
        const int tot = v[0] + v[1] + v[2] + v[3];
        int x = tot;
#pragma unroll
        for (int o = 1; o < 32; o <<= 1) {
            int y = __shfl_up_sync(0xffffffffu, x, o);
            if ((t & 31) >= o) x += y;
        }
        if ((t & 31) == 31) wsum[t >> 5] = x;
        __syncthreads();
        if (t < 32) {
            int w = wsum[t];
#pragma unroll
            for (int o = 1; o < 32; o <<= 1) {
                int y = __shfl_up_sync(0xffffffffu, w, o);
                if (t >= o) w += y;
            }
            wsum[t] = w;
        }
        __syncthreads();
        int excl = x - tot + ((t >= 32) ? wsum[(t >> 5) - 1] : 0) + running;
        int p[4];
        p[0] = excl;
        p[1] = p[0] + v[0];
        p[2] = p[1] + v[1];
        p[3] = p[2] + v[2];
#pragma unroll
        for (int q = 0; q < 4; q++)
            if (idx + q < NN) { ptr[idx + q] = p[q]; cursor[idx + q] = p[q]; }
        __syncthreads();
        if (t == 0) running += wsum[31];
        __syncthreads();
    }
    if (t == 0) ptr[NN] = running;
}

// ---------------------------------------------------------------------------
// Stage B (merged): CSR fill + 3 weight transposes/casts + out bias init.
// ---------------------------------------------------------------------------
#define PW1 (HID * KP1)        // 49152
#define PW2 (HID * HID)        // 65536
#define STAGEB_TOT (NE + PW1 + 2 * PW2 + NN * 2)

__global__ void fill_prep_kernel(const int* __restrict__ src,
                                 const int* __restrict__ dst,
                                 int* __restrict__ cursor, int* __restrict__ csr,
                                 const float* __restrict__ W1a,
                                 const float* __restrict__ W1b,
                                 const float* __restrict__ W2a,
                                 const float* __restrict__ b2b,
                                 __half* __restrict__ w1a,
                                 __half* __restrict__ w1b,
                                 __half* __restrict__ w2a,
                                 float* __restrict__ out) {
    int i = blockIdx.x * blockDim.x + threadIdx.x;
    if (i < NE) {
        int p = atomicAdd(&cursor[__ldg(dst + i)], 1);
        csr[p] = __ldg(src + i);
        return;
    }
    i -= NE;
    if (i < PW1) {
        int n = i / KP1, k = i % KP1;
        float w = (k < INC) ? __ldg(&W1a[(size_t)k * HID + n]) : 0.f;
        w1a[i] = __float2half_rn(w);
        return;
    }
    i -= PW1;
    if (i < PW2) {
        int n = i / HID, k = i % HID;
        w1b[i] = __float2half_rn(__ldg(&W1b[(size_t)k * HID + n]));
        return;
    }
    i -= PW2;
    if (i < PW2) {
        int n = i / HID, k = i % HID;
        w2a[i] = __float2half_rn(__ldg(&W2a[(size_t)k * HID + n]));
        return;
    }
    i -= PW2;
    if (i < NN * 2) out[i] = __ldg(b2b + (i & 1));
}

// ---------------------------------------------------------------------------
// Gather-aggregate (single fp16 plane): z[n] = f[n] + sum_nbr f[nbr].
// Warp per node; lane covers one uint4 (8 fp16 columns). fp32 accum.
// ---------------------------------------------------------------------------
template<int RU4>   // uint4s per row (24 for K=192, 32 for K=256)
__global__ void gather_kernel(const uint4* __restrict__ f,
                              const int* __restrict__ ptr, const int* __restrict__ csr,
                              uint4* __restrict__ z) {
    int n = blockIdx.x * (blockDim.x >> 5) + (threadIdx.x >> 5);
    if (n >= NN) return;
    const int lane = threadIdx.x & 31;
    if (lane >= RU4) return;
    float a[8] = {0, 0, 0, 0, 0, 0, 0, 0};
    acc8(a, __ldg(f + (size_t)n * RU4 + lane));
    const int e0 = __ldg(ptr + n), e1 = __ldg(ptr + n + 1);
    int j = e0;
    for (; j + 3 < e1; j += 4) {
        const size_t b0 = (size_t)__ldg(csr + j)     * RU4;
        const size_t b1 = (size_t)__ldg(csr + j + 1) * RU4;
        const size_t b2 = (size_t)__ldg(csr + j + 2) * RU4;
        const size_t b3 = (size_t)__ldg(csr + j + 3) * RU4;
        uint4 v0 = __ldg(f + b0 + lane), v1 = __ldg(f + b1 + lane);
        uint4 v2 = __ldg(f + b2 + lane), v3 = __ldg(f + b3 + lane);
        acc8(a, v0); acc8(a, v1); acc8(a, v2); acc8(a, v3);
    }
    for (; j < e1; j++) {
        const size_t b0 = (size_t)__ldg(csr + j) * RU4;
        acc8(a, __ldg(f + b0 + lane));
    }
    uint4 o;
    o.x = pack2h(a[0], a[1]);
    o.y = pack2h(a[2], a[3]);
    o.z = pack2h(a[4], a[5]);
    o.w = pack2h(a[6], a[7]);
    z[(size_t)n * RU4 + lane] = o;
}

// ---------------------------------------------------------------------------
// 2-stage cp.async pipelined warp-MMA GEMM: C = A @ B, fp16 x fp16, fp32 acc.
// Stage = 36.9 KB, 2 stages = 73.7 KB -> 2 CTAs/SM (pipeline + cross-CTA overlap).
// CTA tile 128x128, 8 warps 4Mx2N, warp tile 32x64.
// Non-OUTP epilogue: relu(acc+bias) -> single fp16 plane.
// OUTP: relu(acc+bias) projected on w2[256][2], atomicAdd into Cout[M][2].
// ---------------------------------------------------------------------------
#define SROW 72
#define SMAT (128 * SROW * 2)      // 18432 B per tile
#define OFF_A 0
#define OFF_B (SMAT)
#define STG (2 * SMAT)             // 36864 B per stage
#define SMTOT (2 * STG)            // 73728 B

template<bool OUTP>
__global__ __launch_bounds__(256, 2)
void mma_gemm_kernel(const __half* __restrict__ A, int lda,
                     const __half* __restrict__ B, int Kp,
                     const float* __restrict__ bias,
                     __half* __restrict__ C,
                     float* __restrict__ Cout, int M,
                     const float* __restrict__ w2) {
    extern __shared__ __align__(16) char smem[];
    const uint32_t sb = smem_u32(smem);
    const int tid = threadIdx.x, wid = tid >> 5, lane = tid & 31;

    const int bm0 = blockIdx.y * 128;
    const int n0 = blockIdx.x * 128;

    const int arow = tid >> 1;
    const int acol0 = (tid & 1) * 32;
    const int mw = (wid >> 1) * 32;
    const int nw = (wid & 1) * 64;

    const int gRow = bm0 + arow;
    const __half* pA = A + (size_t)(gRow < M ? gRow : 0) * lda + acol0;
    const __half* pB = B + (size_t)(n0 + arow) * Kp + acol0;
    const uint32_t sdst = sb + (uint32_t)(arow * SROW + acol0) * 2;

    const int nchunks = Kp >> 6;

#define PREFETCH(CH)  do { \
        const int _k0 = (CH) << 6; \
        const uint32_t _d = sdst + ((CH) & 1) * STG; \
        _Pragma("unroll") \
        for (int q = 0; q < 4; q++) { \
            cp16(_d + OFF_A + q * 16, pA + _k0 + q * 8); \
            cp16(_d + OFF_B + q * 16, pB + _k0 + q * 8); \
        } \
    } while (0)

    PREFETCH(0);
    asm volatile("cp.async.commit_group;" ::: "memory");
    PREFETCH(1);
    asm volatile("cp.async.commit_group;" ::: "memory");

    float acc[2][8][4];
#pragma unroll
    for (int ms = 0; ms < 2; ms++)
#pragma unroll
        for (int ns = 0; ns < 8; ns++)
#pragma unroll
            for (int q = 0; q < 4; q++) acc[ms][ns][q] = 0.f;

    const int l7 = lane & 7;
    const int aRowAdd = ((lane >> 3) & 1) * 8;
    const int aKAdd = (lane >> 4) * 8;
    const int bl = lane & 15;
    const int bRow = bl & 7;
    const int bKAdd = ((bl >> 3) & 1) * 8;

    for (int ch = 0; ch < nchunks; ch++) {
        asm volatile("cp.async.wait_group 1;" ::: "memory");
        __syncthreads();

        const uint32_t st = sb + (ch & 1) * STG;
#pragma unroll
        for (int kk = 0; kk < 64; kk += 16) {
            uint32_t av[2][4], bv[8][2];
#pragma unroll
            for (int ms = 0; ms < 2; ms++) {
                uint32_t ra = st + (uint32_t)((mw + ms * 16 + l7 + aRowAdd) * SROW + kk + aKAdd) * 2;
                ldm_x4(av[ms], ra + OFF_A);
            }
#pragma unroll
            for (int ns = 0; ns < 8; ns++) {
                uint32_t rb = st + (uint32_t)((nw + ns * 8 + bRow) * SROW + kk + bKAdd) * 2;
                ldm_x2(bv[ns], rb + OFF_B);
            }
#pragma unroll
            for (int ms = 0; ms < 2; ms++)
#pragma unroll
                for (int ns = 0; ns < 8; ns++)
                    mma_f16(acc[ms][ns], av[ms], bv[ns]);
        }
        __syncthreads();
        if (ch + 2 < nchunks) PREFETCH(ch + 2);
        asm volatile("cp.async.commit_group;" ::: "memory");
    }
#undef PREFETCH

    const int r = lane >> 2;
    const int cp = (lane & 3) * 2;

    if (OUTP) {
        float s[2][2][2];
#pragma unroll
        for (int ms = 0; ms < 2; ms++)
#pragma unroll
            for (int rh = 0; rh < 2; rh++) { s[ms][rh][0] = 0.f; s[ms][rh][1] = 0.f; }
#pragma unroll
        for (int ms = 0; ms < 2; ms++)
#pragma unroll
            for (int ns = 0; ns < 8; ns++) {
                const int col = n0 + nw + ns * 8 + cp;
                const float2 bb = *(const float2*)(bias + col);
                const float2 w0 = *(const float2*)(w2 + col * 2);
                const float2 w1 = *(const float2*)(w2 + (col + 1) * 2);
                float v0 = fmaxf(acc[ms][ns][0] + bb.x, 0.f);
                float v1 = fmaxf(acc[ms][ns][1] + bb.y, 0.f);
                float v2 = fmaxf(acc[ms][ns][2] + bb.x, 0.f);
                float v3 = fmaxf(acc[ms][ns][3] + bb.y, 0.f);
                s[ms][0][0] += v0 * w0.x + v1 * w1.x;
                s[ms][0][1] += v0 * w0.y + v1 * w1.y;
                s[ms][1][0] += v2 * w0.x + v3 * w1.x;
                s[ms][1][1] += v2 * w0.y + v3 * w1.y;
            }
#pragma unroll
        for (int ms = 0; ms < 2; ms++)
#pragma unroll
            for (int rh = 0; rh < 2; rh++)
#pragma unroll
                for (int oc = 0; oc < 2; oc++) {
                    float v = s[ms][rh][oc];
                    v += __shfl_xor_sync(0xffffffffu, v, 1);
                    v += __shfl_xor_sync(0xffffffffu, v, 2);
                    s[ms][rh][oc] = v;
                }
        if ((lane & 3) == 0) {
#pragma unroll
            for (int ms = 0; ms < 2; ms++)
#pragma unroll
                for (int rh = 0; rh < 2; rh++) {
                    const int row = bm0 + mw + ms * 16 + r + rh * 8;
                    if (row < M) {
                        atomicAdd(Cout + (size_t)row * 2 + 0, s[ms][rh][0]);
                        atomicAdd(Cout + (size_t)row * 2 + 1, s[ms][rh][1]);
                    }
                }
        }
    } else {
#pragma unroll
        for (int ms = 0; ms < 2; ms++)
#pragma unroll
            for (int ns = 0; ns < 8; ns++) {
                const int col = n0 + nw + ns * 8 + cp;
                const float2 bb = *(const float2*)(bias + col);
                const int row0 = bm0 + mw + ms * 16 + r;
                float v0 = fmaxf(acc[ms][ns][0] + bb.x, 0.f);
                float v1 = fmaxf(acc[ms][ns][1] + bb.y, 0.f);
                float v2 = fmaxf(acc[ms][ns][2] + bb.x, 0.f);
                float v3 = fmaxf(acc[ms][ns][3] + bb.y, 0.f);
#pragma unroll
                for (int rh = 0; rh < 2; rh++) {
                    const int row = row0 + rh * 8;
                    if (row >= M) continue;
                    *(uint32_t*)(C + (size_t)row * HID + col) =
                        pack2h(rh ? v2 : v0, rh ? v3 : v1);
                }
            }
    }
}

// ---------------------------------------------------------------------------
extern "C" void kernel_launch(void* const* d_in, const int* in_sizes, int n_in,
                              void* d_out, int out_size) {
    const float* x   = (const float*)d_in[0];
    const int*   ei  = (const int*)d_in[1];
    const float* W1a = (const float*)d_in[2];
    const float* b1a = (const float*)d_in[3];
    const float* W1b = (const float*)d_in[4];
    const float* b1b = (const float*)d_in[5];
    const float* W2a = (const float*)d_in[6];
    const float* b2a = (const float*)d_in[7];
    const float* W2b = (const float*)d_in[8];
    const float* b2b = (const float*)d_in[9];
    float* out = (float*)d_out;

    const int* src = ei;
    const int* dst = ei + NE;

    int *cnt, *ptr, *cursor, *csr;
    __half *xp, *z1, *h1, *h, *z2;
    __half *w1a, *w1b, *w2a;
    cudaGetSymbolAddress((void**)&cnt,    g_cnt);
    cudaGetSymbolAddress((void**)&ptr,    g_ptr);
    cudaGetSymbolAddress((void**)&cursor, g_cursor);
    cudaGetSymbolAddress((void**)&csr,    g_csr);
    cudaGetSymbolAddress((void**)&xp,     g_x);
    cudaGetSymbolAddress((void**)&z1,     g_z1);
    cudaGetSymbolAddress((void**)&h1,     g_h1);
    cudaGetSymbolAddress((void**)&h,      g_h);
    cudaGetSymbolAddress((void**)&z2,     g_z2);
    cudaGetSymbolAddress((void**)&w1a,    g_w1a);
    cudaGetSymbolAddress((void**)&w1b,    g_w1b);
    cudaGetSymbolAddress((void**)&w2a,    g_w2a);

    cudaFuncSetAttribute(mma_gemm_kernel<false>,
                         cudaFuncAttributeMaxDynamicSharedMemorySize, SMTOT);
    cudaFuncSetAttribute(mma_gemm_kernel<true>,
                         cudaFuncAttributeMaxDynamicSharedMemorySize, SMTOT);

    const dim3 gemmGrid(2, (NN + 127) / 128);
    const int nodeGrid = (NN + 7) / 8;

    // ---- CSR build + pad + prep (merged stages) ----
    cudaMemsetAsync(cnt, 0, sizeof(int) * NN);
    hist_pad_kernel<<<(STAGEA_TOT + 255) / 256, 256>>>(dst, x, cnt, xp);
    scan_kernel<<<1, 1024>>>(cnt, ptr, cursor);
    fill_prep_kernel<<<(STAGEB_TOT + 255) / 256, 256>>>(
        src, dst, cursor, csr, W1a, W1b, W2a, b2b, w1a, w1b, w2a, out);

    // ---- layer 1 ----
    gather_kernel<KP1 / 8><<<nodeGrid, 256>>>((const uint4*)xp, ptr, csr, (uint4*)z1);
    mma_gemm_kernel<false><<<gemmGrid, 256, SMTOT>>>(
        z1, KP1, w1a, KP1, b1a, h1, nullptr, NN, nullptr);
    mma_gemm_kernel<false><<<gemmGrid, 256, SMTOT>>>(
        h1, HID, w1b, HID, b1b, h, nullptr, NN, nullptr);

    // ---- layer 2 ----
    gather_kernel<HID / 8><<<nodeGrid, 256>>>((const uint4*)h, ptr, csr, (uint4*)z2);
    mma_gemm_kernel<true><<<gemmGrid, 256, SMTOT>>>(
        z2, HID, w2a, HID, b2a, nullptr, out, NN, W2b);
}

// round 16
// speedup vs baseline: 1.2072x; 1.0263x over previous
#include <cuda_runtime.h>
#include <cuda_fp16.h>
#include <cstdint>

#define NN 50000
#define NE 800000
#define INC 165
#define HID 256
#define KP1 192              // K=165 padded to multiple of 64

// ---------------- scratch (no runtime allocation allowed) ----------------
__device__ int   g_cnt[NN];
__device__ int   g_ptr[NN + 1];
__device__ int   g_cursor[NN];
__device__ int   g_csr[NE];
__device__ __half g_x [(size_t)NN * KP1];
__device__ __half g_z1[(size_t)NN * KP1];
__device__ __half g_h1[(size_t)NN * HID];
__device__ __half g_h [(size_t)NN * HID];
__device__ __half g_z2[(size_t)NN * HID];
__device__ __half g_w1a[HID * KP1];
__device__ __half g_w1b[HID * HID];
__device__ __half g_w2a[HID * HID];

// ---------------- PTX helpers ----------------
__device__ __forceinline__ uint32_t smem_u32(const void* p) {
    uint32_t a;
    asm("{ .reg .u64 t; cvta.to.shared.u64 t, %1; cvt.u32.u64 %0, t; }" : "=r"(a) : "l"(p));
    return a;
}
__device__ __forceinline__ void ldm_x4(uint32_t* r, uint32_t addr) {
    asm volatile("ldmatrix.sync.aligned.m8n8.x4.shared.b16 {%0,%1,%2,%3}, [%4];"
        : "=r"(r[0]), "=r"(r[1]), "=r"(r[2]), "=r"(r[3]) : "r"(addr));
}
__device__ __forceinline__ void ldm_x2(uint32_t* r, uint32_t addr) {
    asm volatile("ldmatrix.sync.aligned.m8n8.x2.shared.b16 {%0,%1}, [%2];"
        : "=r"(r[0]), "=r"(r[1]) : "r"(addr));
}
__device__ __forceinline__ void mma_f16(float* c, const uint32_t* a, const uint32_t* b) {
    asm volatile("mma.sync.aligned.m16n8k16.row.col.f32.f16.f16.f32 "
        "{%0,%1,%2,%3}, {%4,%5,%6,%7}, {%8,%9}, {%0,%1,%2,%3};"
        : "+f"(c[0]), "+f"(c[1]), "+f"(c[2]), "+f"(c[3])
        : "r"(a[0]), "r"(a[1]), "r"(a[2]), "r"(a[3]), "r"(b[0]), "r"(b[1]));
}
__device__ __forceinline__ void cp16(uint32_t dst, const void* src) {
    asm volatile("cp.async.ca.shared.global [%0], [%1], 16;" :: "r"(dst), "l"(src));
}
__device__ __forceinline__ uint32_t pack2h(float v0, float v1) {
    __half2 h = __floats2half2_rn(v0, v1);
    return *(uint32_t*)&h;
}
__device__ __forceinline__ void acc8(float* a, uint4 h) {
    const uint32_t hu[4] = {h.x, h.y, h.z, h.w};
#pragma unroll
    for (int q = 0; q < 4; q++) {
        float2 fh = __half22float2(*(const __half2*)&hu[q]);
        a[2 * q]     += fh.x;
        a[2 * q + 1] += fh.y;
    }
}
__device__ __forceinline__ uint32_t hadd2u(uint32_t a, uint32_t b) {
    __half2 r = __hadd2(*(const __half2*)&a, *(const __half2*)&b);
    return *(uint32_t*)&r;
}
__device__ __forceinline__ uint4 hadd2u4(uint4 a, uint4 b) {
    return make_uint4(hadd2u(a.x, b.x), hadd2u(a.y, b.y),
                      hadd2u(a.z, b.z), hadd2u(a.w, b.w));
}

// ---------------------------------------------------------------------------
// Stage A (merged): hist over edges + pad/convert x. Disjoint thread ranges.
// ---------------------------------------------------------------------------
#define PADN (NN * (KP1 / 4))          // 2,400,000 pad work-items (4 cols each)
#define STAGEA_TOT (NE + PADN)

__global__ void hist_pad_kernel(const int* __restrict__ dst,
                                const float* __restrict__ x,
                                int* __restrict__ cnt,
                                __half* __restrict__ xo) {
    int i = blockIdx.x * blockDim.x + threadIdx.x;
    if (i < NE) {
        atomicAdd(&cnt[__ldg(dst + i)], 1);
        return;
    }
    i -= NE;
    if (i >= PADN) return;
    int n = i / (KP1 / 4), c = (i % (KP1 / 4)) * 4;
    float v[4];
#pragma unroll
    for (int q = 0; q < 4; q++) {
        int cc = c + q;
        v[q] = (cc < INC) ? __ldg(&x[(size_t)n * INC + cc]) : 0.f;
    }
    *(uint32_t*)(xo + (size_t)n * KP1 + c)     = pack2h(v[0], v[1]);
    *(uint32_t*)(xo + (size_t)n * KP1 + c + 2) = pack2h(v[2], v[3]);
}

// ---------------------------------------------------------------------------
// Scan: single block, 4 elements/thread per iteration (13 iterations).
// ---------------------------------------------------------------------------
__global__ void scan_kernel(const int* __restrict__ cnt,
                            int* __restrict__ ptr, int* __restrict__ cursor) {
    __shared__ int wsum[32];
    __shared__ int running;
    const int t = threadIdx.x;
    if (t == 0) running = 0;
    __syncthreads();
    for (int base = 0; base < NN; base += 4096) {
        const int idx = base + t * 4;
        int v[4];
#pragma unroll
        for (int q = 0; q < 4; q++)
            v[q] = (idx + q < NN) ? cnt[idx + q] : 0;
        const int tot = v[0] + v[1] + v[2] + v[3];
        int x = tot;
#pragma unroll
        for (int o = 1; o < 32; o <<= 1) {
            int y = __shfl_up_sync(0xffffffffu, x, o);
            if ((t & 31) >= o) x += y;
        }
        if ((t & 31) == 31) wsum[t >> 5] = x;
        __syncthreads();
        if (t < 32) {
            int w = wsum[t];
#pragma unroll
            for (int o = 1; o < 32; o <<= 1) {
                int y = __shfl_up_sync(0xffffffffu, w, o);
                if (t >= o) w += y;
            }
            wsum[t] = w;
        }
        __syncthreads();
        int excl = x - tot + ((t >= 32) ? wsum[(t >> 5) - 1] : 0) + running;
        int p[4];
        p[0] = excl;
        p[1] = p[0] + v[0];
        p[2] = p[1] + v[1];
        p[3] = p[2] + v[2];
#pragma unroll
        for (int q = 0; q < 4; q++)
            if (idx + q < NN) { ptr[idx + q] = p[q]; cursor[idx + q] = p[q]; }
        __syncthreads();
        if (t == 0) running += wsum[31];
        __syncthreads();
    }
    if (t == 0) ptr[NN] = running;
}

// ---------------------------------------------------------------------------
// Stage B (merged): CSR fill + 3 weight transposes/casts + out bias init.
// ---------------------------------------------------------------------------
#define PW1 (HID * KP1)        // 49152
#define PW2 (HID * HID)        // 65536
#define STAGEB_TOT (NE + PW1 + 2 * PW2 + NN * 2)

__global__ void fill_prep_kernel(const int* __restrict__ src,
                                 const int* __restrict__ dst,
                                 int* __restrict__ cursor, int* __restrict__ csr,
                                 const float* __restrict__ W1a,
                                 const float* __restrict__ W1b,
                                 const float* __restrict__ W2a,
                                 const float* __restrict__ b2b,
                                 __half* __restrict__ w1a,
                                 __half* __restrict__ w1b,
                                 __half* __restrict__ w2a,
                                 float* __restrict__ out) {
    int i = blockIdx.x * blockDim.x + threadIdx.x;
    if (i < NE) {
        int p = atomicAdd(&cursor[__ldg(dst + i)], 1);
        csr[p] = __ldg(src + i);
        return;
    }
    i -= NE;
    if (i < PW1) {
        int n = i / KP1, k = i % KP1;
        float w = (k < INC) ? __ldg(&W1a[(size_t)k * HID + n]) : 0.f;
        w1a[i] = __float2half_rn(w);
        return;
    }
    i -= PW1;
    if (i < PW2) {
        int n = i / HID, k = i % HID;
        w1b[i] = __float2half_rn(__ldg(&W1b[(size_t)k * HID + n]));
        return;
    }
    i -= PW2;
    if (i < PW2) {
        int n = i / HID, k = i % HID;
        w2a[i] = __float2half_rn(__ldg(&W2a[(size_t)k * HID + n]));
        return;
    }
    i -= PW2;
    if (i < NN * 2) out[i] = __ldg(b2b + (i & 1));
}

// ---------------------------------------------------------------------------
// Gather-aggregate: z[n] = f[n] + sum_nbr f[nbr].
// Warp per node; lane covers one uint4 (8 fp16 columns).
// Neighbor PAIRS pre-reduced in fp16 (1 HADD2 rounding per pair), then
// accumulated in fp32 — cuts the issue-bound cvt/add chain ~1.6x.
// ---------------------------------------------------------------------------
template<int RU4>   // uint4s per row (24 for K=192, 32 for K=256)
__global__ void gather_kernel(const uint4* __restrict__ f,
                              const int* __restrict__ ptr, const int* __restrict__ csr,
                              uint4* __restrict__ z) {
    int n = blockIdx.x * (blockDim.x >> 5) + (threadIdx.x >> 5);
    if (n >= NN) return;
    const int lane = threadIdx.x & 31;
    if (lane >= RU4) return;
    float a[8] = {0, 0, 0, 0, 0, 0, 0, 0};
    acc8(a, __ldg(f + (size_t)n * RU4 + lane));
    const int e0 = __ldg(ptr + n), e1 = __ldg(ptr + n + 1);
    int j = e0;
    for (; j + 3 < e1; j += 4) {
        const size_t b0 = (size_t)__ldg(csr + j)     * RU4;
        const size_t b1 = (size_t)__ldg(csr + j + 1) * RU4;
        const size_t b2 = (size_t)__ldg(csr + j + 2) * RU4;
        const size_t b3 = (size_t)__ldg(csr + j + 3) * RU4;
        uint4 v0 = __ldg(f + b0 + lane), v1 = __ldg(f + b1 + lane);
        uint4 v2 = __ldg(f + b2 + lane), v3 = __ldg(f + b3 + lane);
        acc8(a, hadd2u4(v0, v1));
        acc8(a, hadd2u4(v2, v3));
    }
    if (j + 1 < e1) {
        const size_t b0 = (size_t)__ldg(csr + j)     * RU4;
        const size_t b1 = (size_t)__ldg(csr + j + 1) * RU4;
        uint4 v0 = __ldg(f + b0 + lane), v1 = __ldg(f + b1 + lane);
        acc8(a, hadd2u4(v0, v1));
        j += 2;
    }
    if (j < e1) {
        const size_t b0 = (size_t)__ldg(csr + j) * RU4;
        acc8(a, __ldg(f + b0 + lane));
    }
    uint4 o;
    o.x = pack2h(a[0], a[1]);
    o.y = pack2h(a[2], a[3]);
    o.z = pack2h(a[4], a[5]);
    o.w = pack2h(a[6], a[7]);
    z[(size_t)n * RU4 + lane] = o;
}

// ---------------------------------------------------------------------------
// 2-stage cp.async pipelined warp-MMA GEMM: C = A @ B, fp16 x fp16, fp32 acc.
// Stage = 36.9 KB, 2 stages = 73.7 KB -> 2 CTAs/SM (pipeline + cross-CTA overlap).
// CTA tile 128x128, 8 warps 4Mx2N, warp tile 32x64.
// Non-OUTP epilogue: relu(acc+bias) -> single fp16 plane.
// OUTP: relu(acc+bias) projected on w2[256][2], atomicAdd into Cout[M][2].
// ---------------------------------------------------------------------------
#define SROW 72
#define SMAT (128 * SROW * 2)      // 18432 B per tile
#define OFF_A 0
#define OFF_B (SMAT)
#define STG (2 * SMAT)             // 36864 B per stage
#define SMTOT (2 * STG)            // 73728 B

template<bool OUTP>
__global__ __launch_bounds__(256, 2)
void mma_gemm_kernel(const __half* __restrict__ A, int lda,
                     const __half* __restrict__ B, int Kp,
                     const float* __restrict__ bias,
                     __half* __restrict__ C,
                     float* __restrict__ Cout, int M,
                     const float* __restrict__ w2) {
    extern __shared__ __align__(16) char smem[];
    const uint32_t sb = smem_u32(smem);
    const int tid = threadIdx.x, wid = tid >> 5, lane = tid & 31;

    const int bm0 = blockIdx.y * 128;
    const int n0 = blockIdx.x * 128;

    const int arow = tid >> 1;
    const int acol0 = (tid & 1) * 32;
    const int mw = (wid >> 1) * 32;
    const int nw = (wid & 1) * 64;

    const int gRow = bm0 + arow;
    const __half* pA = A + (size_t)(gRow < M ? gRow : 0) * lda + acol0;
    const __half* pB = B + (size_t)(n0 + arow) * Kp + acol0;
    const uint32_t sdst = sb + (uint32_t)(arow * SROW + acol0) * 2;

    const int nchunks = Kp >> 6;

#define PREFETCH(CH)  do { \
        const int _k0 = (CH) << 6; \
        const uint32_t _d = sdst + ((CH) & 1) * STG; \
        _Pragma("unroll") \
        for (int q = 0; q < 4; q++) { \
            cp16(_d + OFF_A + q * 16, pA + _k0 + q * 8); \
            cp16(_d + OFF_B + q * 16, pB + _k0 + q * 8); \
        } \
    } while (0)

    PREFETCH(0);
    asm volatile("cp.async.commit_group;" ::: "memory");
    PREFETCH(1);
    asm volatile("cp.async.commit_group;" ::: "memory");

    float acc[2][8][4];
#pragma unroll
    for (int ms = 0; ms < 2; ms++)
#pragma unroll
        for (int ns = 0; ns < 8; ns++)
#pragma unroll
            for (int q = 0; q < 4; q++) acc[ms][ns][q] = 0.f;

    const int l7 = lane & 7;
    const int aRowAdd = ((lane >> 3) & 1) * 8;
    const int aKAdd = (lane >> 4) * 8;
    const int bl = lane & 15;
    const int bRow = bl & 7;
    const int bKAdd = ((bl >> 3) & 1) * 8;

    for (int ch = 0; ch < nchunks; ch++) {
        asm volatile("cp.async.wait_group 1;" ::: "memory");
        __syncthreads();

        const uint32_t st = sb + (ch & 1) * STG;
#pragma unroll
        for (int kk = 0; kk < 64; kk += 16) {
            uint32_t av[2][4], bv[8][2];
#pragma unroll
            for (int ms = 0; ms < 2; ms++) {
                uint32_t ra = st + (uint32_t)((mw + ms * 16 + l7 + aRowAdd) * SROW + kk + aKAdd) * 2;
                ldm_x4(av[ms], ra + OFF_A);
            }
#pragma unroll
            for (int ns = 0; ns < 8; ns++) {
                uint32_t rb = st + (uint32_t)((nw + ns * 8 + bRow) * SROW + kk + bKAdd) * 2;
                ldm_x2(bv[ns], rb + OFF_B);
            }
#pragma unroll
            for (int ms = 0; ms < 2; ms++)
#pragma unroll
                for (int ns = 0; ns < 8; ns++)
                    mma_f16(acc[ms][ns], av[ms], bv[ns]);
        }
        __syncthreads();
        if (ch + 2 < nchunks) PREFETCH(ch + 2);
        asm volatile("cp.async.commit_group;" ::: "memory");
    }
#undef PREFETCH

    const int r = lane >> 2;
    const int cp = (lane & 3) * 2;

    if (OUTP) {
        float s[2][2][2];
#pragma unroll
        for (int ms = 0; ms < 2; ms++)
#pragma unroll
            for (int rh = 0; rh < 2; rh++) { s[ms][rh][0] = 0.f; s[ms][rh][1] = 0.f; }
#pragma unroll
        for (int ms = 0; ms < 2; ms++)
#pragma unroll
            for (int ns = 0; ns < 8; ns++) {
                const int col = n0 + nw + ns * 8 + cp;
                const float2 bb = *(const float2*)(bias + col);
                const float2 w0 = *(const float2*)(w2 + col * 2);
                const float2 w1 = *(const float2*)(w2 + (col + 1) * 2);
                float v0 = fmaxf(acc[ms][ns][0] + bb.x, 0.f);
                float v1 = fmaxf(acc[ms][ns][1] + bb.y, 0.f);
                float v2 = fmaxf(acc[ms][ns][2] + bb.x, 0.f);
                float v3 = fmaxf(acc[ms][ns][3] + bb.y, 0.f);
                s[ms][0][0] += v0 * w0.x + v1 * w1.x;
                s[ms][0][1] += v0 * w0.y + v1 * w1.y;
                s[ms][1][0] += v2 * w0.x + v3 * w1.x;
                s[ms][1][1] += v2 * w0.y + v3 * w1.y;
            }
#pragma unroll
        for (int ms = 0; ms < 2; ms++)
#pragma unroll
            for (int rh = 0; rh < 2; rh++)
#pragma unroll
                for (int oc = 0; oc < 2; oc++) {
                    float v = s[ms][rh][oc];
                    v += __shfl_xor_sync(0xffffffffu, v, 1);
                    v += __shfl_xor_sync(0xffffffffu, v, 2);
                    s[ms][rh][oc] = v;
                }
        if ((lane & 3) == 0) {
#pragma unroll
            for (int ms = 0; ms < 2; ms++)
#pragma unroll
                for (int rh = 0; rh < 2; rh++) {
                    const int row = bm0 + mw + ms * 16 + r + rh * 8;
                    if (row < M) {
                        atomicAdd(Cout + (size_t)row * 2 + 0, s[ms][rh][0]);
                        atomicAdd(Cout + (size_t)row * 2 + 1, s[ms][rh][1]);
                    }
                }
        }
    } else {
#pragma unroll
        for (int ms = 0; ms < 2; ms++)
#pragma unroll
            for (int ns = 0; ns < 8; ns++) {
                const int col = n0 + nw + ns * 8 + cp;
                const float2 bb = *(const float2*)(bias + col);
                const int row0 = bm0 + mw + ms * 16 + r;
                float v0 = fmaxf(acc[ms][ns][0] + bb.x, 0.f);
                float v1 = fmaxf(acc[ms][ns][1] + bb.y, 0.f);
                float v2 = fmaxf(acc[ms][ns][2] + bb.x, 0.f);
                float v3 = fmaxf(acc[ms][ns][3] + bb.y, 0.f);
#pragma unroll
                for (int rh = 0; rh < 2; rh++) {
                    const int row = row0 + rh * 8;
                    if (row >= M) continue;
                    *(uint32_t*)(C + (size_t)row * HID + col) =
                        pack2h(rh ? v2 : v0, rh ? v3 : v1);
                }
            }
    }
}

// ---------------------------------------------------------------------------
extern "C" void kernel_launch(void* const* d_in, const int* in_sizes, int n_in,
                              void* d_out, int out_size) {
    const float* x   = (const float*)d_in[0];
    const int*   ei  = (const int*)d_in[1];
    const float* W1a = (const float*)d_in[2];
    const float* b1a = (const float*)d_in[3];
    const float* W1b = (const float*)d_in[4];
    const float* b1b = (const float*)d_in[5];
    const float* W2a = (const float*)d_in[6];
    const float* b2a = (const float*)d_in[7];
    const float* W2b = (const float*)d_in[8];
    const float* b2b = (const float*)d_in[9];
    float* out = (float*)d_out;

    const int* src = ei;
    const int* dst = ei + NE;

    int *cnt, *ptr, *cursor, *csr;
    __half *xp, *z1, *h1, *h, *z2;
    __half *w1a, *w1b, *w2a;
    cudaGetSymbolAddress((void**)&cnt,    g_cnt);
    cudaGetSymbolAddress((void**)&ptr,    g_ptr);
    cudaGetSymbolAddress((void**)&cursor, g_cursor);
    cudaGetSymbolAddress((void**)&csr,    g_csr);
    cudaGetSymbolAddress((void**)&xp,     g_x);
    cudaGetSymbolAddress((void**)&z1,     g_z1);
    cudaGetSymbolAddress((void**)&h1,     g_h1);
    cudaGetSymbolAddress((void**)&h,      g_h);
    cudaGetSymbolAddress((void**)&z2,     g_z2);
    cudaGetSymbolAddress((void**)&w1a,    g_w1a);
    cudaGetSymbolAddress((void**)&w1b,    g_w1b);
    cudaGetSymbolAddress((void**)&w2a,    g_w2a);

    cudaFuncSetAttribute(mma_gemm_kernel<false>,
                         cudaFuncAttributeMaxDynamicSharedMemorySize, SMTOT);
    cudaFuncSetAttribute(mma_gemm_kernel<true>,
                         cudaFuncAttributeMaxDynamicSharedMemorySize, SMTOT);

    const dim3 gemmGrid(2, (NN + 127) / 128);
    const int nodeGrid = (NN + 7) / 8;

    // ---- CSR build + pad + prep (merged stages) ----
    cudaMemsetAsync(cnt, 0, sizeof(int) * NN);
    hist_pad_kernel<<<(STAGEA_TOT + 255) / 256, 256>>>(dst, x, cnt, xp);
    scan_kernel<<<1, 1024>>>(cnt, ptr, cursor);
    fill_prep_kernel<<<(STAGEB_TOT + 255) / 256, 256>>>(
        src, dst, cursor, csr, W1a, W1b, W2a, b2b, w1a, w1b, w2a, out);

    // ---- layer 1 ----
    gather_kernel<KP1 / 8><<<nodeGrid, 256>>>((const uint4*)xp, ptr, csr, (uint4*)z1);
    mma_gemm_kernel<false><<<gemmGrid, 256, SMTOT>>>(
        z1, KP1, w1a, KP1, b1a, h1, nullptr, NN, nullptr);
    mma_gemm_kernel<false><<<gemmGrid, 256, SMTOT>>>(
        h1, HID, w1b, HID, b1b, h, nullptr, NN, nullptr);

    // ---- layer 2 ----
    gather_kernel<HID / 8><<<nodeGrid, 256>>>((const uint4*)h, ptr, csr, (uint4*)z2);
    mma_gemm_kernel<true><<<gemmGrid, 256, SMTOT>>>(
        z2, HID, w2a, HID, b2a, nullptr, out, NN, W2b);
}